// round 2
// baseline (speedup 1.0000x reference)
#include <cuda_runtime.h>

// Problem constants
#define BT    65536   // B*T
#define CDIM  128
#define HDIM  64
#define TSEQ  512

// q/k/v scratch (device globals: allocation-free rule)
__device__ float g_q[BT * HDIM];
__device__ float g_k[BT * HDIM];
__device__ float g_v[BT * HDIM];

// ---------------------------------------------------------------------------
// Kernel 1: gate GEMM + sigmoid-gate + QKV GEMM for a 128-token tile.
// Parameter order matches d_in order: x, Wg, bg, Wk, Wq, Wv.
// ---------------------------------------------------------------------------
__global__ __launch_bounds__(256, 1)
void head_k1_gate_qkv(const float* __restrict__ x,
                      const float* __restrict__ Wg,
                      const float* __restrict__ bg,
                      const float* __restrict__ Wk,
                      const float* __restrict__ Wq,
                      const float* __restrict__ Wv)
{
    extern __shared__ float sm[];
    float* xs = sm;               // [128][132]
    float* ws = sm + 128 * 132;   // [128][132] then [128][196]

    const int tid  = threadIdx.x;
    const int tok0 = blockIdx.x * 128;

    // load x tile
    for (int i = tid; i < 128 * 128; i += 256) {
        int t = i >> 7, c = i & 127;
        xs[t * 132 + c] = x[(size_t)(tok0 + t) * CDIM + c];
    }
    // load Wg
    for (int i = tid; i < 128 * 128; i += 256) {
        int c = i >> 7, d = i & 127;
        ws[c * 132 + d] = Wg[i];
    }
    __syncthreads();

    // ---- phase 1: gate = x @ Wg, thread tile 4 tok x 16 ch ----
    // 128 tokens / 4 = 32 row groups ; 128 ch / 16 = 8 col groups ; 32*8 = 256
    const int tr = (tid >> 3) * 4;     // token row group: 0..124
    const int dc = (tid & 7) * 16;     // channel col group: 0..112
    float acc[4][16];
    #pragma unroll
    for (int i = 0; i < 4; i++)
        #pragma unroll
        for (int j = 0; j < 16; j++) acc[i][j] = 0.f;

    #pragma unroll 2
    for (int c = 0; c < 128; ++c) {
        float xv[4];
        #pragma unroll
        for (int i = 0; i < 4; i++) xv[i] = xs[(tr + i) * 132 + c];
        const float4* wp = reinterpret_cast<const float4*>(ws + c * 132 + dc);
        float wv[16];
        reinterpret_cast<float4*>(wv)[0] = wp[0];
        reinterpret_cast<float4*>(wv)[1] = wp[1];
        reinterpret_cast<float4*>(wv)[2] = wp[2];
        reinterpret_cast<float4*>(wv)[3] = wp[3];
        #pragma unroll
        for (int i = 0; i < 4; i++)
            #pragma unroll
            for (int j = 0; j < 16; j++)
                acc[i][j] = fmaf(xv[i], wv[j], acc[i][j]);
    }
    __syncthreads();

    // sigmoid-gate, write xg in place (each (t,d) owned by exactly one thread)
    #pragma unroll
    for (int i = 0; i < 4; i++) {
        const int t = tr + i;
        #pragma unroll
        for (int j = 0; j < 16; j++) {
            const int d   = dc + j;
            float pre     = acc[i][j] + bg[d];
            float gate    = 1.f / (1.f + __expf(-pre));
            xs[t * 132 + d] = xs[t * 132 + d] * gate;
        }
    }
    __syncthreads();

    // load packed W[q|k|v] -> [128][196]; e: 0..63 q, 64..127 k, 128..191 v
    for (int i = tid; i < 128 * 192; i += 256) {
        int c = i / 192, e = i % 192;
        float w;
        if (e < 64)       w = Wq[c * 64 + e];
        else if (e < 128) w = Wk[c * 64 + (e - 64)];
        else              w = Wv[c * 64 + (e - 128)];
        ws[c * 196 + e] = w;
    }
    __syncthreads();

    // ---- phase 2: [q|k|v] = xg @ W, thread tile 8 tok x 12 ch ----
    // 128/8 = 16 row groups ; 192/12 = 16 col groups ; 16*16 = 256
    const int rg = (tid >> 4) * 8;     // 0..120
    const int eg = (tid & 15) * 12;    // 0..180
    float acc2[8][12];
    #pragma unroll
    for (int i = 0; i < 8; i++)
        #pragma unroll
        for (int j = 0; j < 12; j++) acc2[i][j] = 0.f;

    #pragma unroll 2
    for (int c = 0; c < 128; ++c) {
        float xv[8];
        #pragma unroll
        for (int i = 0; i < 8; i++) xv[i] = xs[(rg + i) * 132 + c];
        const float4* wp = reinterpret_cast<const float4*>(ws + c * 196 + eg);
        float wv[12];
        reinterpret_cast<float4*>(wv)[0] = wp[0];
        reinterpret_cast<float4*>(wv)[1] = wp[1];
        reinterpret_cast<float4*>(wv)[2] = wp[2];
        #pragma unroll
        for (int i = 0; i < 8; i++)
            #pragma unroll
            for (int j = 0; j < 12; j++)
                acc2[i][j] = fmaf(xv[i], wv[j], acc2[i][j]);
    }

    // scatter to q/k/v scratch
    #pragma unroll
    for (int i = 0; i < 8; i++) {
        const size_t tok = (size_t)(tok0 + rg + i);
        #pragma unroll
        for (int j = 0; j < 12; j++) {
            const int e = eg + j;
            const float v = acc2[i][j];
            if (e < 64)       g_q[tok * 64 + e]         = v;
            else if (e < 128) g_k[tok * 64 + (e - 64)]  = v;
            else              g_v[tok * 64 + (e - 128)] = v;
        }
    }
}

// ---------------------------------------------------------------------------
// Kernel 2: causal flash attention (fp32).
// grid = (4 q-tiles, 128 batches), 256 threads.
// ---------------------------------------------------------------------------
__global__ __launch_bounds__(256, 1)
void head_k2_attn(float* __restrict__ out)
{
    extern __shared__ float sm[];
    float* Qt      = sm;                  // [64][132]
    float* Kt      = Qt + 64 * 132;       // [64][132]
    float* Vs      = Kt + 64 * 132;       // [128][68]
    float* Ssm     = Vs + 128 * 68;       // [128][132]
    float* m_s     = Ssm + 128 * 132;     // [128]
    float* l_s     = m_s + 128;           // [128]
    float* alpha_s = l_s + 128;           // [128]
    float* red     = alpha_s + 128;       // [256]

    const int tid = threadIdx.x;
    const int qt  = blockIdx.x;           // 0..3
    const int b   = blockIdx.y;           // 0..127
    const int q0  = qt * 128;
    const size_t base = (size_t)b * TSEQ * HDIM;

    const float scale = 0.088388347648318447f;   // 1/sqrt(128)

    // load Q^T (scaled)
    for (int i = tid; i < 128 * 64; i += 256) {
        int r = i >> 6, h = i & 63;
        Qt[h * 132 + r] = g_q[base + (size_t)(q0 + r) * 64 + h] * scale;
    }
    if (tid < 128) { m_s[tid] = -1e30f; l_s[tid] = 0.f; }

    const int qr  = (tid >> 4) * 8;   // 8 query rows (16 groups)
    const int kc8 = (tid & 15) * 8;   // 8 key cols (16 groups)
    const int hc  = (tid & 15) * 4;   // 4 head cols (16 groups)
    float acc[8][4];
    #pragma unroll
    for (int i = 0; i < 8; i++)
        #pragma unroll
        for (int j = 0; j < 4; j++) acc[i][j] = 0.f;

    for (int jt = 0; jt <= qt; ++jt) {
        const int k0 = jt * 128;
        __syncthreads();   // prev-iter PV readers done; Q/init visible on iter 0

        // load K^T and V for this tile
        for (int i = tid; i < 128 * 64; i += 256) {
            int r = i >> 6, h = i & 63;
            Kt[h * 132 + r] = g_k[base + (size_t)(k0 + r) * 64 + h];
            Vs[r * 68 + h]  = g_v[base + (size_t)(k0 + r) * 64 + h];
        }
        __syncthreads();

        // ---- S = Q K^T, thread tile 8x8 ----
        float s[8][8];
        #pragma unroll
        for (int i = 0; i < 8; i++)
            #pragma unroll
            for (int j = 0; j < 8; j++) s[i][j] = 0.f;

        #pragma unroll 2
        for (int c = 0; c < 64; ++c) {
            float qf[8], kf[8];
            reinterpret_cast<float4*>(qf)[0] = *reinterpret_cast<const float4*>(Qt + c * 132 + qr);
            reinterpret_cast<float4*>(qf)[1] = *reinterpret_cast<const float4*>(Qt + c * 132 + qr + 4);
            reinterpret_cast<float4*>(kf)[0] = *reinterpret_cast<const float4*>(Kt + c * 132 + kc8);
            reinterpret_cast<float4*>(kf)[1] = *reinterpret_cast<const float4*>(Kt + c * 132 + kc8 + 4);
            #pragma unroll
            for (int i = 0; i < 8; i++)
                #pragma unroll
                for (int j = 0; j < 8; j++)
                    s[i][j] = fmaf(qf[i], kf[j], s[i][j]);
        }

        // write S with causal mask (diagonal tile only; k0 == q0 there)
        const bool diag = (jt == qt);
        #pragma unroll
        for (int i = 0; i < 8; i++) {
            const int ql = qr + i;
            #pragma unroll
            for (int j = 0; j < 8; j++) {
                float sv = s[i][j];
                if (diag && (kc8 + j) > ql) sv = -1e30f;
                Ssm[ql * 132 + kc8 + j] = sv;
            }
        }
        __syncthreads();

        // ---- online softmax: 2 threads per row ----
        const int rr = tid >> 1;
        const int hf = tid & 1;
        {
            const float* row = Ssm + rr * 132 + hf * 64;
            float mx = -1e30f;
            #pragma unroll 4
            for (int c = 0; c < 64; ++c) mx = fmaxf(mx, row[c]);
            red[tid] = mx;
        }
        __syncthreads();
        if (hf == 0) {
            float mt = fmaxf(red[tid], red[tid + 1]);
            float mo = m_s[rr];
            float mn = fmaxf(mo, mt);
            alpha_s[rr] = __expf(mo - mn);
            m_s[rr] = mn;
        }
        __syncthreads();
        {
            const float mn = m_s[rr];
            float* row = Ssm + rr * 132 + hf * 64;
            float srow = 0.f;
            #pragma unroll 4
            for (int c = 0; c < 64; ++c) {
                float p = __expf(row[c] - mn);
                row[c] = p;
                srow += p;
            }
            red[tid] = srow;
        }
        __syncthreads();
        if (hf == 0) l_s[rr] = l_s[rr] * alpha_s[rr] + red[tid] + red[tid + 1];

        // rescale accumulators
        float al[8];
        #pragma unroll
        for (int i = 0; i < 8; i++) al[i] = alpha_s[qr + i];
        #pragma unroll
        for (int i = 0; i < 8; i++)
            #pragma unroll
            for (int j = 0; j < 4; j++) acc[i][j] *= al[i];

        // ---- O += P @ V, thread tile 8q x 4h ----
        #pragma unroll 2
        for (int kk = 0; kk < 128; ++kk) {
            float4 vv = *reinterpret_cast<const float4*>(Vs + kk * 68 + hc);
            #pragma unroll
            for (int i = 0; i < 8; i++) {
                float p = Ssm[(qr + i) * 132 + kk];
                acc[i][0] = fmaf(p, vv.x, acc[i][0]);
                acc[i][1] = fmaf(p, vv.y, acc[i][1]);
                acc[i][2] = fmaf(p, vv.z, acc[i][2]);
                acc[i][3] = fmaf(p, vv.w, acc[i][3]);
            }
        }
    }

    __syncthreads();
    // epilogue: out = acc / l
    #pragma unroll
    for (int i = 0; i < 8; i++) {
        const float linv = 1.f / l_s[qr + i];
        float4 o;
        o.x = acc[i][0] * linv;
        o.y = acc[i][1] * linv;
        o.z = acc[i][2] * linv;
        o.w = acc[i][3] * linv;
        *reinterpret_cast<float4*>(out + base + (size_t)(q0 + qr + i) * 64 + hc) = o;
    }
}

// ---------------------------------------------------------------------------
extern "C" void kernel_launch(void* const* d_in, const int* in_sizes, int n_in,
                              void* d_out, int out_size)
{
    const float* x  = (const float*)d_in[0];
    const float* Wg = (const float*)d_in[1];
    const float* bg = (const float*)d_in[2];
    const float* Wk = (const float*)d_in[3];
    const float* Wq = (const float*)d_in[4];
    const float* Wv = (const float*)d_in[5];
    float* out = (float*)d_out;

    const size_t smem1 = (size_t)(128 * 132 + 128 * 196) * sizeof(float);              // 167,936 B
    const size_t smem2 = (size_t)(64 * 132 * 2 + 128 * 68 + 128 * 132 + 3 * 128 + 256)
                         * sizeof(float);                                              // 172,544 B

    cudaFuncSetAttribute(head_k1_gate_qkv,
                         cudaFuncAttributeMaxDynamicSharedMemorySize, (int)smem1);
    cudaFuncSetAttribute(head_k2_attn,
                         cudaFuncAttributeMaxDynamicSharedMemorySize, (int)smem2);

    head_k1_gate_qkv<<<BT / 128, 256, smem1>>>(x, Wg, bg, Wk, Wq, Wv);
    head_k2_attn<<<dim3(4, 128), 256, smem2>>>(out);
}

// round 5
// speedup vs baseline: 1.9994x; 1.9994x over previous
#include <cuda_runtime.h>
#include <cuda_bf16.h>
#include <cstdint>

// Problem constants
#define BT    65536   // B*T
#define CDIM  128
#define HDIM  64
#define TSEQ  512
#define SCALE 0.088388347648318447f   // 1/sqrt(128)

// q/k scratch bf16 hi/lo in [B][T][H]; v scratch bf16 hi/lo in [B][H][T]
__device__ __nv_bfloat16 g_qhi[BT * HDIM];
__device__ __nv_bfloat16 g_qlo[BT * HDIM];
__device__ __nv_bfloat16 g_khi[BT * HDIM];
__device__ __nv_bfloat16 g_klo[BT * HDIM];
__device__ __nv_bfloat16 g_vhi[BT * HDIM];
__device__ __nv_bfloat16 g_vlo[BT * HDIM];

// ---------------------------------------------------------------------------
// helpers
// ---------------------------------------------------------------------------
// pack two floats -> bf16x2 word (lo -> bits[15:0], hi -> bits[31:16])
__device__ __forceinline__ uint32_t pack_bf16(float lo, float hi) {
    uint32_t r;
    asm("cvt.rn.bf16x2.f32 %0, %1, %2;" : "=r"(r) : "f"(hi), "f"(lo));
    return r;
}
__device__ __forceinline__ float bf16_residual(float v) {
    return v - __bfloat162float(__float2bfloat16(v));
}
// hi word + lo word from a float pair
__device__ __forceinline__ void split_pack(float v0, float v1,
                                           uint32_t& hi, uint32_t& lo) {
    __nv_bfloat16 h0 = __float2bfloat16(v0);
    __nv_bfloat16 h1 = __float2bfloat16(v1);
    __nv_bfloat162 hh; hh.x = h0; hh.y = h1;
    hi = *reinterpret_cast<uint32_t*>(&hh);
    lo = pack_bf16(v0 - __bfloat162float(h0), v1 - __bfloat162float(h1));
}
// m16n8k16 bf16 MMA, f32 accumulate (family-neutral; runs on tensor cores)
__device__ __forceinline__ void mma_bf16(float* d, const uint32_t* a,
                                         const uint32_t* b) {
    asm volatile(
        "mma.sync.aligned.m16n8k16.row.col.f32.bf16.bf16.f32 "
        "{%0,%1,%2,%3}, {%4,%5,%6,%7}, {%8,%9}, {%0,%1,%2,%3};"
        : "+f"(d[0]), "+f"(d[1]), "+f"(d[2]), "+f"(d[3])
        : "r"(a[0]), "r"(a[1]), "r"(a[2]), "r"(a[3]), "r"(b[0]), "r"(b[1]));
}

// ---------------------------------------------------------------------------
// Kernel 1: gate GEMM + sigmoid-gate + QKV GEMM (bf16x3 HMMA).
// 256 threads (8 warps x 16 rows). Row stride 136 bf16 = 68 words (= 4 mod 32
// -> all fragment LDS conflict-free).
// smem bytes: AH[128*136*2]=34816 @0, AL @34816, BH[192*136*2]=52224 @69632,
//             BL @121856, bg @174080 (512B). total 174592.
// vT overlay (64x132 f32 = 33792B) reuses AH after phase-2 MMAs complete.
// ---------------------------------------------------------------------------
#define K1_SMEM 174592

__global__ __launch_bounds__(256, 1)
void head_k1_gate_qkv(const float* __restrict__ x,
                      const float* __restrict__ Wg,
                      const float* __restrict__ bg,
                      const float* __restrict__ Wk,
                      const float* __restrict__ Wq,
                      const float* __restrict__ Wv)
{
    extern __shared__ char smc[];
    __nv_bfloat16* AH = reinterpret_cast<__nv_bfloat16*>(smc);
    __nv_bfloat16* AL = reinterpret_cast<__nv_bfloat16*>(smc + 34816);
    __nv_bfloat16* BH = reinterpret_cast<__nv_bfloat16*>(smc + 69632);
    __nv_bfloat16* BL = reinterpret_cast<__nv_bfloat16*>(smc + 121856);
    float*         bgs = reinterpret_cast<float*>(smc + 174080);
    float*         vT  = reinterpret_cast<float*>(smc);          // overlay

    const uint32_t* AHw = reinterpret_cast<const uint32_t*>(AH);
    const uint32_t* ALw = reinterpret_cast<const uint32_t*>(AL);
    const uint32_t* BHw = reinterpret_cast<const uint32_t*>(BH);
    const uint32_t* BLw = reinterpret_cast<const uint32_t*>(BL);

    const int tid   = threadIdx.x;
    const int wid   = tid >> 5;
    const int lane  = tid & 31;
    const int g     = lane >> 2;        // group (row within fragment)
    const int qq    = lane & 3;
    const int q2    = qq * 2;
    const int wbase = wid * 16;
    const int tok0  = blockIdx.x * 128;
    const int bb    = tok0 >> 9;
    const int t0    = tok0 & 511;

    // ---- load x -> A hi/lo ----
    for (int i = tid; i < 128 * 128; i += 256) {
        int t = i >> 7, c = i & 127;
        float v = x[(size_t)(tok0 + t) * CDIM + c];
        __nv_bfloat16 h = __float2bfloat16(v);
        AH[t * 136 + c] = h;
        AL[t * 136 + c] = __float2bfloat16(v - __bfloat162float(h));
    }
    // ---- load Wg^T -> B hi/lo : B[n=d][k=c] = Wg[c][d] ----
    for (int i = tid; i < 128 * 128; i += 256) {
        int c = i >> 7, d = i & 127;
        float v = Wg[c * 128 + d];
        __nv_bfloat16 h = __float2bfloat16(v);
        BH[d * 136 + c] = h;
        BL[d * 136 + c] = __float2bfloat16(v - __bfloat162float(h));
    }
    if (tid < 128) bgs[tid] = bg[tid];
    __syncthreads();

    // ---- phase 1: gate = x @ Wg (M=16/warp, N=128, K=128) ----
    float acc[16][4];
    #pragma unroll
    for (int j = 0; j < 16; j++)
        #pragma unroll
        for (int t = 0; t < 4; t++) acc[j][t] = 0.f;

    #pragma unroll
    for (int kk = 0; kk < 8; ++kk) {
        const int kw = kk * 8 + qq;
        const int r0 = wbase + g;
        uint32_t ah[4], al[4];
        ah[0] = AHw[r0 * 68 + kw];       ah[1] = AHw[(r0 + 8) * 68 + kw];
        ah[2] = AHw[r0 * 68 + kw + 4];   ah[3] = AHw[(r0 + 8) * 68 + kw + 4];
        al[0] = ALw[r0 * 68 + kw];       al[1] = ALw[(r0 + 8) * 68 + kw];
        al[2] = ALw[r0 * 68 + kw + 4];   al[3] = ALw[(r0 + 8) * 68 + kw + 4];
        #pragma unroll
        for (int j = 0; j < 16; ++j) {
            const int n = j * 8 + g;
            uint32_t bh[2] = { BHw[n * 68 + kw], BHw[n * 68 + kw + 4] };
            uint32_t bl[2] = { BLw[n * 68 + kw], BLw[n * 68 + kw + 4] };
            mma_bf16(acc[j], ah, bh);
            mma_bf16(acc[j], ah, bl);
            mma_bf16(acc[j], al, bh);
        }
    }

    // ---- gate epilogue: xg = x * sigmoid(gate + bg), rewrite A (own rows) ----
    #pragma unroll
    for (int j = 0; j < 16; ++j) {
        const int col = j * 8 + q2;
        #pragma unroll
        for (int hf = 0; hf < 2; ++hf) {
            const int r = wbase + g + hf * 8;
            __nv_bfloat162 hw = *reinterpret_cast<__nv_bfloat162*>(&AH[r * 136 + col]);
            __nv_bfloat162 lw = *reinterpret_cast<__nv_bfloat162*>(&AL[r * 136 + col]);
            float x0 = __bfloat162float(hw.x) + __bfloat162float(lw.x);
            float x1 = __bfloat162float(hw.y) + __bfloat162float(lw.y);
            float c0 = acc[j][hf * 2 + 0], c1 = acc[j][hf * 2 + 1];
            float g0 = 1.f / (1.f + __expf(-(c0 + bgs[col])));
            float g1 = 1.f / (1.f + __expf(-(c1 + bgs[col + 1])));
            float xg0 = x0 * g0, xg1 = x1 * g1;
            uint32_t hiw, low;
            split_pack(xg0, xg1, hiw, low);
            *reinterpret_cast<uint32_t*>(&AH[r * 136 + col]) = hiw;
            *reinterpret_cast<uint32_t*>(&AL[r * 136 + col]) = low;
        }
    }
    __syncthreads();

    // ---- load W[q|k|v]^T -> B (192 rows): e 0..63 q, 64..127 k, 128..191 v ----
    for (int i = tid; i < 128 * 192; i += 256) {
        int c = i / 192, e = i % 192;
        float v;
        if (e < 64)       v = Wq[c * 64 + e];
        else if (e < 128) v = Wk[c * 64 + (e - 64)];
        else              v = Wv[c * 64 + (e - 128)];
        __nv_bfloat16 h = __float2bfloat16(v);
        BH[e * 136 + c] = h;
        BL[e * 136 + c] = __float2bfloat16(v - __bfloat162float(h));
    }
    __syncthreads();

    // ---- phase 2: [q|k|v] = xg @ W (N=192) ----
    float acc2[24][4];
    #pragma unroll
    for (int j = 0; j < 24; j++)
        #pragma unroll
        for (int t = 0; t < 4; t++) acc2[j][t] = 0.f;

    #pragma unroll
    for (int kk = 0; kk < 8; ++kk) {
        const int kw = kk * 8 + qq;
        const int r0 = wbase + g;
        uint32_t ah[4], al[4];
        ah[0] = AHw[r0 * 68 + kw];       ah[1] = AHw[(r0 + 8) * 68 + kw];
        ah[2] = AHw[r0 * 68 + kw + 4];   ah[3] = AHw[(r0 + 8) * 68 + kw + 4];
        al[0] = ALw[r0 * 68 + kw];       al[1] = ALw[(r0 + 8) * 68 + kw];
        al[2] = ALw[r0 * 68 + kw + 4];   al[3] = ALw[(r0 + 8) * 68 + kw + 4];
        #pragma unroll
        for (int j = 0; j < 24; ++j) {
            const int n = j * 8 + g;
            uint32_t bh[2] = { BHw[n * 68 + kw], BHw[n * 68 + kw + 4] };
            uint32_t bl[2] = { BLw[n * 68 + kw], BLw[n * 68 + kw + 4] };
            mma_bf16(acc2[j], ah, bh);
            mma_bf16(acc2[j], ah, bl);
            mma_bf16(acc2[j], al, bh);
        }
    }
    __syncthreads();   // all A reads done before vT overlay writes

    // ---- epilogue: q (scaled) & k -> [B][T][H] bf16 hi/lo; v -> vT smem ----
    uint32_t* gqh = reinterpret_cast<uint32_t*>(g_qhi);
    uint32_t* gql = reinterpret_cast<uint32_t*>(g_qlo);
    uint32_t* gkh = reinterpret_cast<uint32_t*>(g_khi);
    uint32_t* gkl = reinterpret_cast<uint32_t*>(g_klo);
    #pragma unroll
    for (int j = 0; j < 8; ++j) {             // q cols 0..63
        const int h = j * 8 + q2;
        #pragma unroll
        for (int hf = 0; hf < 2; ++hf) {
            const int r = wbase + g + hf * 8;
            uint32_t hiw, low;
            split_pack(acc2[j][hf * 2] * SCALE, acc2[j][hf * 2 + 1] * SCALE, hiw, low);
            size_t widx = (size_t)(tok0 + r) * 32 + (h >> 1);
            gqh[widx] = hiw; gql[widx] = low;
        }
    }
    #pragma unroll
    for (int j = 8; j < 16; ++j) {            // k cols
        const int h = (j - 8) * 8 + q2;
        #pragma unroll
        for (int hf = 0; hf < 2; ++hf) {
            const int r = wbase + g + hf * 8;
            uint32_t hiw, low;
            split_pack(acc2[j][hf * 2], acc2[j][hf * 2 + 1], hiw, low);
            size_t widx = (size_t)(tok0 + r) * 32 + (h >> 1);
            gkh[widx] = hiw; gkl[widx] = low;
        }
    }
    #pragma unroll
    for (int j = 16; j < 24; ++j) {           // v cols -> vT [h][132 t]
        const int h = (j - 16) * 8 + q2;
        const int r = wbase + g;
        vT[h * 132 + r]           = acc2[j][0];
        vT[(h + 1) * 132 + r]     = acc2[j][1];
        vT[h * 132 + r + 8]       = acc2[j][2];
        vT[(h + 1) * 132 + r + 8] = acc2[j][3];
    }
    __syncthreads();

    // ---- v: coalesced bf16 hi/lo stores to [B][H][T] ----
    uint32_t* gvh = reinterpret_cast<uint32_t*>(g_vhi);
    uint32_t* gvl = reinterpret_cast<uint32_t*>(g_vlo);
    for (int i = tid; i < 64 * 64; i += 256) {
        int h = i >> 6, tw = i & 63;
        int t = tw * 2;
        float f0 = vT[h * 132 + t];
        float f1 = vT[h * 132 + t + 1];
        uint32_t hiw, low;
        split_pack(f0, f1, hiw, low);
        size_t widx = ((size_t)bb * 64 + h) * 256 + ((t0 + t) >> 1);
        gvh[widx] = hiw; gvl[widx] = low;
    }
}

// ---------------------------------------------------------------------------
// Kernel 2: causal flash attention, bf16x3 HMMA, register online softmax.
// grid (4 q-tiles, 128 batches), 256 threads (8 warps x 16 q-rows).
// smem words: QH[128*36] QL KH KL (4608 each), VH[64*68] VL (4352 each).
// ---------------------------------------------------------------------------
#define K2_SMEM 108544

__global__ __launch_bounds__(256, 1)
void head_k2_attn(float* __restrict__ out)
{
    extern __shared__ char smc[];
    uint32_t* QHw = reinterpret_cast<uint32_t*>(smc);
    uint32_t* QLw = QHw + 4608;
    uint32_t* KHw = QLw + 4608;
    uint32_t* KLw = KHw + 4608;
    uint32_t* VHw = KLw + 4608;
    uint32_t* VLw = VHw + 4352;

    const int tid   = threadIdx.x;
    const int wid   = tid >> 5;
    const int lane  = tid & 31;
    const int g     = lane >> 2;
    const int qq    = lane & 3;
    const int q2    = qq * 2;
    const int wbase = wid * 16;
    const int qt    = blockIdx.x;
    const int b     = blockIdx.y;
    const int q0    = qt * 128;

    const uint32_t* gqh = reinterpret_cast<const uint32_t*>(g_qhi);
    const uint32_t* gql = reinterpret_cast<const uint32_t*>(g_qlo);
    const uint32_t* gkh = reinterpret_cast<const uint32_t*>(g_khi);
    const uint32_t* gkl = reinterpret_cast<const uint32_t*>(g_klo);
    const uint32_t* gvh = reinterpret_cast<const uint32_t*>(g_vhi);
    const uint32_t* gvl = reinterpret_cast<const uint32_t*>(g_vlo);

    // ---- load Q tile (pre-scaled in k1) ----
    {
        size_t qbase = ((size_t)b * 512 + q0) * 32;
        for (int i = tid; i < 128 * 32; i += 256) {
            int t = i >> 5, w = i & 31;
            QHw[t * 36 + w] = gqh[qbase + (size_t)t * 32 + w];
            QLw[t * 36 + w] = gql[qbase + (size_t)t * 32 + w];
        }
    }
    __syncthreads();

    // ---- cache Q fragments (k=64 -> 4 ksteps) ----
    uint32_t qh[4][4], ql[4][4];
    #pragma unroll
    for (int kk = 0; kk < 4; ++kk) {
        const int kw = kk * 8 + qq;
        const int r0 = wbase + g;
        qh[kk][0] = QHw[r0 * 36 + kw];       qh[kk][1] = QHw[(r0 + 8) * 36 + kw];
        qh[kk][2] = QHw[r0 * 36 + kw + 4];   qh[kk][3] = QHw[(r0 + 8) * 36 + kw + 4];
        ql[kk][0] = QLw[r0 * 36 + kw];       ql[kk][1] = QLw[(r0 + 8) * 36 + kw];
        ql[kk][2] = QLw[r0 * 36 + kw + 4];   ql[kk][3] = QLw[(r0 + 8) * 36 + kw + 4];
    }

    float o[8][4];
    #pragma unroll
    for (int j = 0; j < 8; j++)
        #pragma unroll
        for (int t = 0; t < 4; t++) o[j][t] = 0.f;
    float m0 = -1e30f, m1 = -1e30f, l0 = 0.f, l1 = 0.f;

    for (int jt = 0; jt <= qt; ++jt) {
        const int k0 = jt * 128;
        __syncthreads();
        // ---- load K,V tiles ----
        {
            size_t kbase = ((size_t)b * 512 + k0) * 32;
            for (int i = tid; i < 128 * 32; i += 256) {
                int t = i >> 5, w = i & 31;
                KHw[t * 36 + w] = gkh[kbase + (size_t)t * 32 + w];
                KLw[t * 36 + w] = gkl[kbase + (size_t)t * 32 + w];
            }
            size_t vbase = (size_t)b * 64 * 256 + (k0 >> 1);
            for (int i = tid; i < 64 * 64; i += 256) {
                int h = i >> 6, w = i & 63;
                VHw[h * 68 + w] = gvh[vbase + (size_t)h * 256 + w];
                VLw[h * 68 + w] = gvl[vbase + (size_t)h * 256 + w];
            }
        }
        __syncthreads();

        // ---- S = Q K^T (16 rows x 128 keys per warp) ----
        float s[16][4];
        #pragma unroll
        for (int j = 0; j < 16; j++)
            #pragma unroll
            for (int t = 0; t < 4; t++) s[j][t] = 0.f;

        #pragma unroll
        for (int kk = 0; kk < 4; ++kk) {
            const int kw = kk * 8 + qq;
            #pragma unroll
            for (int j = 0; j < 16; ++j) {
                const int n = j * 8 + g;
                uint32_t bh[2] = { KHw[n * 36 + kw], KHw[n * 36 + kw + 4] };
                uint32_t bl[2] = { KLw[n * 36 + kw], KLw[n * 36 + kw + 4] };
                mma_bf16(s[j], qh[kk], bh);
                mma_bf16(s[j], qh[kk], bl);
                mma_bf16(s[j], ql[kk], bh);
            }
        }

        // ---- causal mask on diagonal tile ----
        if (jt == qt) {
            const int r0 = q0 + wbase + g;
            #pragma unroll
            for (int j = 0; j < 16; ++j) {
                const int c0 = k0 + j * 8 + q2;
                if (c0     > r0)     s[j][0] = -1e30f;
                if (c0 + 1 > r0)     s[j][1] = -1e30f;
                if (c0     > r0 + 8) s[j][2] = -1e30f;
                if (c0 + 1 > r0 + 8) s[j][3] = -1e30f;
            }
        }

        // ---- online softmax (quad shuffles per row) ----
        float mx0 = -1e30f, mx1 = -1e30f;
        #pragma unroll
        for (int j = 0; j < 16; ++j) {
            mx0 = fmaxf(mx0, fmaxf(s[j][0], s[j][1]));
            mx1 = fmaxf(mx1, fmaxf(s[j][2], s[j][3]));
        }
        mx0 = fmaxf(mx0, __shfl_xor_sync(0xffffffffu, mx0, 1));
        mx0 = fmaxf(mx0, __shfl_xor_sync(0xffffffffu, mx0, 2));
        mx1 = fmaxf(mx1, __shfl_xor_sync(0xffffffffu, mx1, 1));
        mx1 = fmaxf(mx1, __shfl_xor_sync(0xffffffffu, mx1, 2));
        const float mn0 = fmaxf(m0, mx0), mn1 = fmaxf(m1, mx1);
        const float a0 = __expf(m0 - mn0), a1 = __expf(m1 - mn1);
        m0 = mn0; m1 = mn1;
        l0 *= a0; l1 *= a1;
        #pragma unroll
        for (int j = 0; j < 8; ++j) {
            o[j][0] *= a0; o[j][1] *= a0; o[j][2] *= a1; o[j][3] *= a1;
        }
        float s0 = 0.f, s1 = 0.f;
        #pragma unroll
        for (int j = 0; j < 16; ++j) {
            s[j][0] = __expf(s[j][0] - mn0); s0 += s[j][0];
            s[j][1] = __expf(s[j][1] - mn0); s0 += s[j][1];
            s[j][2] = __expf(s[j][2] - mn1); s1 += s[j][2];
            s[j][3] = __expf(s[j][3] - mn1); s1 += s[j][3];
        }
        s0 += __shfl_xor_sync(0xffffffffu, s0, 1);
        s0 += __shfl_xor_sync(0xffffffffu, s0, 2);
        s1 += __shfl_xor_sync(0xffffffffu, s1, 1);
        s1 += __shfl_xor_sync(0xffffffffu, s1, 2);
        l0 += s0; l1 += s1;

        // ---- O += P @ V (lane-local P->A-fragment conversion) ----
        #pragma unroll
        for (int kk2 = 0; kk2 < 8; ++kk2) {
            const int j0 = kk2 * 2, j1 = j0 + 1;
            uint32_t ah[4], al[4];
            ah[0] = pack_bf16(s[j0][0], s[j0][1]);
            ah[1] = pack_bf16(s[j0][2], s[j0][3]);
            ah[2] = pack_bf16(s[j1][0], s[j1][1]);
            ah[3] = pack_bf16(s[j1][2], s[j1][3]);
            al[0] = pack_bf16(bf16_residual(s[j0][0]), bf16_residual(s[j0][1]));
            al[1] = pack_bf16(bf16_residual(s[j0][2]), bf16_residual(s[j0][3]));
            al[2] = pack_bf16(bf16_residual(s[j1][0]), bf16_residual(s[j1][1]));
            al[3] = pack_bf16(bf16_residual(s[j1][2]), bf16_residual(s[j1][3]));
            #pragma unroll
            for (int jn = 0; jn < 8; ++jn) {
                const int hN = jn * 8 + g;
                uint32_t vh[2] = { VHw[hN * 68 + kk2 * 8 + qq],
                                   VHw[hN * 68 + kk2 * 8 + qq + 4] };
                uint32_t vl[2] = { VLw[hN * 68 + kk2 * 8 + qq],
                                   VLw[hN * 68 + kk2 * 8 + qq + 4] };
                mma_bf16(o[jn], ah, vh);
                mma_bf16(o[jn], ah, vl);
                mma_bf16(o[jn], al, vh);
            }
        }
    }

    // ---- epilogue: out = O / l, [B][T][H] fp32 ----
    const float i0 = 1.f / l0, i1 = 1.f / l1;
    const int r0 = q0 + wbase + g;
    const size_t ob = (size_t)b * TSEQ * HDIM;
    #pragma unroll
    for (int jn = 0; jn < 8; ++jn) {
        const int h = jn * 8 + q2;
        float2 v0 = make_float2(o[jn][0] * i0, o[jn][1] * i0);
        float2 v1 = make_float2(o[jn][2] * i1, o[jn][3] * i1);
        *reinterpret_cast<float2*>(out + ob + (size_t)r0 * 64 + h)       = v0;
        *reinterpret_cast<float2*>(out + ob + (size_t)(r0 + 8) * 64 + h) = v1;
    }
}

// ---------------------------------------------------------------------------
extern "C" void kernel_launch(void* const* d_in, const int* in_sizes, int n_in,
                              void* d_out, int out_size)
{
    const float* x  = (const float*)d_in[0];
    const float* Wg = (const float*)d_in[1];
    const float* bg = (const float*)d_in[2];
    const float* Wk = (const float*)d_in[3];
    const float* Wq = (const float*)d_in[4];
    const float* Wv = (const float*)d_in[5];
    float* out = (float*)d_out;

    cudaFuncSetAttribute(head_k1_gate_qkv,
                         cudaFuncAttributeMaxDynamicSharedMemorySize, K1_SMEM);
    cudaFuncSetAttribute(head_k2_attn,
                         cudaFuncAttributeMaxDynamicSharedMemorySize, K2_SMEM);

    head_k1_gate_qkv<<<BT / 128, 256, K1_SMEM>>>(x, Wg, bg, Wk, Wq, Wv);
    head_k2_attn<<<dim3(4, 128), 256, K2_SMEM>>>(out);
}

// round 6
// speedup vs baseline: 3.4188x; 1.7100x over previous
#include <cuda_runtime.h>
#include <cuda_bf16.h>
#include <cstdint>

// Problem constants
#define BT    65536   // B*T
#define CDIM  128
#define HDIM  64
#define TSEQ  512
#define SCALE 0.088388347648318447f   // 1/sqrt(128)

// q/k scratch bf16 hi/lo in [B][T][H]; v scratch bf16 hi/lo in [B][H][T]
__device__ __nv_bfloat16 g_qhi[BT * HDIM];
__device__ __nv_bfloat16 g_qlo[BT * HDIM];
__device__ __nv_bfloat16 g_khi[BT * HDIM];
__device__ __nv_bfloat16 g_klo[BT * HDIM];
__device__ __nv_bfloat16 g_vhi[BT * HDIM];
__device__ __nv_bfloat16 g_vlo[BT * HDIM];

// pre-split weight images (k0 output), row-major [n][k], k stride 128 bf16
__device__ __nv_bfloat16 g_wgh[128 * 128];
__device__ __nv_bfloat16 g_wgl[128 * 128];
__device__ __nv_bfloat16 g_wqkvh[192 * 128];
__device__ __nv_bfloat16 g_wqkvl[192 * 128];

// ---------------------------------------------------------------------------
// helpers
// ---------------------------------------------------------------------------
__device__ __forceinline__ uint32_t smem_u32(const void* p) {
    uint32_t a;
    asm("{ .reg .u64 t; cvta.to.shared.u64 t, %1; cvt.u32.u64 %0, t; }"
        : "=r"(a) : "l"(p));
    return a;
}
__device__ __forceinline__ uint32_t pack_bf16(float lo, float hi) {
    uint32_t r;
    asm("cvt.rn.bf16x2.f32 %0, %1, %2;" : "=r"(r) : "f"(hi), "f"(lo));
    return r;
}
__device__ __forceinline__ float bf16_residual(float v) {
    return v - __bfloat162float(__float2bfloat16(v));
}
__device__ __forceinline__ void split_pack(float v0, float v1,
                                           uint32_t& hi, uint32_t& lo) {
    __nv_bfloat16 h0 = __float2bfloat16(v0);
    __nv_bfloat16 h1 = __float2bfloat16(v1);
    __nv_bfloat162 hh; hh.x = h0; hh.y = h1;
    hi = *reinterpret_cast<uint32_t*>(&hh);
    lo = pack_bf16(v0 - __bfloat162float(h0), v1 - __bfloat162float(h1));
}
__device__ __forceinline__ void mma_bf16(float* d, const uint32_t* a,
                                         const uint32_t* b) {
    asm volatile(
        "mma.sync.aligned.m16n8k16.row.col.f32.bf16.bf16.f32 "
        "{%0,%1,%2,%3}, {%4,%5,%6,%7}, {%8,%9}, {%0,%1,%2,%3};"
        : "+f"(d[0]), "+f"(d[1]), "+f"(d[2]), "+f"(d[3])
        : "r"(a[0]), "r"(a[1]), "r"(a[2]), "r"(a[3]), "r"(b[0]), "r"(b[1]));
}
__device__ __forceinline__ void cp_async16(uint32_t smem_dst, const void* gsrc) {
    asm volatile("cp.async.cg.shared.global [%0], [%1], 16;"
                 :: "r"(smem_dst), "l"(gsrc) : "memory");
}
#define CP_COMMIT() asm volatile("cp.async.commit_group;" ::: "memory")
#define CP_WAIT0()  asm volatile("cp.async.wait_group 0;" ::: "memory")

// ---------------------------------------------------------------------------
// Kernel 0: one-time weight split into bf16 hi/lo global images.
// g_wg*[d][c] = Wg[c][d] ; g_wqkv*[e][c] = {Wq,Wk,Wv}[c][e'] packed.
// ---------------------------------------------------------------------------
__global__ __launch_bounds__(256, 4)
void head_k0_split(const float* __restrict__ Wg,
                   const float* __restrict__ Wk,
                   const float* __restrict__ Wq,
                   const float* __restrict__ Wv)
{
    int i = blockIdx.x * 256 + threadIdx.x;
    if (i < 128 * 128) {
        int d = i >> 7, c = i & 127;
        float v = Wg[c * 128 + d];
        __nv_bfloat16 h = __float2bfloat16(v);
        g_wgh[i] = h;
        g_wgl[i] = __float2bfloat16(v - __bfloat162float(h));
    } else if (i < 128 * 128 + 192 * 128) {
        int j = i - 128 * 128;
        int e = j >> 7, c = j & 127;
        float v;
        if (e < 64)       v = Wq[c * 64 + e];
        else if (e < 128) v = Wk[c * 64 + (e - 64)];
        else              v = Wv[c * 64 + (e - 128)];
        __nv_bfloat16 h = __float2bfloat16(v);
        g_wqkvh[j] = h;
        g_wqkvl[j] = __float2bfloat16(v - __bfloat162float(h));
    }
}

// ---------------------------------------------------------------------------
// Kernel 1: gate GEMM + sigmoid-gate + QKV GEMM (bf16x3 HMMA), cp.async weights.
// 256 threads (8 warps x 16 rows). Row stride 136 bf16 (= 68 words, 4 mod 32).
// smem bytes: AH @0 (34816), AL @34816, BH @69632 (52224), BL @121856,
//             bg @174080 (512B). total 174592.
// ---------------------------------------------------------------------------
#define K1_SMEM 174592

__global__ __launch_bounds__(256, 1)
void head_k1_gate_qkv(const float* __restrict__ x,
                      const float* __restrict__ bg)
{
    extern __shared__ char smc[];
    const uint32_t sbase = smem_u32(smc);
    __nv_bfloat16* AH = reinterpret_cast<__nv_bfloat16*>(smc);
    __nv_bfloat16* AL = reinterpret_cast<__nv_bfloat16*>(smc + 34816);
    float*         bgs = reinterpret_cast<float*>(smc + 174080);
    float*         vT  = reinterpret_cast<float*>(smc);          // overlay

    const uint32_t* AHw = reinterpret_cast<const uint32_t*>(AH);
    const uint32_t* ALw = reinterpret_cast<const uint32_t*>(AL);
    const uint32_t* BHw = reinterpret_cast<const uint32_t*>(smc + 69632);
    const uint32_t* BLw = reinterpret_cast<const uint32_t*>(smc + 121856);

    const int tid   = threadIdx.x;
    const int wid   = tid >> 5;
    const int lane  = tid & 31;
    const int g     = lane >> 2;
    const int qq    = lane & 3;
    const int q2    = qq * 2;
    const int wbase = wid * 16;
    const int tok0  = blockIdx.x * 128;
    const int bb    = tok0 >> 9;
    const int t0    = tok0 & 511;

    // ---- issue Wg hi/lo -> B via cp.async (rows 0..127, 16 chunks/row) ----
    {
        const char* wh = reinterpret_cast<const char*>(g_wgh);
        const char* wl = reinterpret_cast<const char*>(g_wgl);
        for (int i = tid; i < 2048; i += 256) {
            int row = i >> 4, ch = i & 15;
            uint32_t dof = (uint32_t)(row * 272 + ch * 16);
            cp_async16(sbase + 69632 + dof,  wh + row * 256 + ch * 16);
            cp_async16(sbase + 121856 + dof, wl + row * 256 + ch * 16);
        }
        CP_COMMIT();
    }

    // ---- load + split x -> A hi/lo (overlaps the weight copies) ----
    for (int i = tid; i < 128 * 128; i += 256) {
        int t = i >> 7, c = i & 127;
        float v = x[(size_t)(tok0 + t) * CDIM + c];
        __nv_bfloat16 h = __float2bfloat16(v);
        AH[t * 136 + c] = h;
        AL[t * 136 + c] = __float2bfloat16(v - __bfloat162float(h));
    }
    if (tid < 128) bgs[tid] = bg[tid];
    CP_WAIT0();
    __syncthreads();

    // ---- phase 1: gate = x @ Wg ----
    float acc[16][4];
    #pragma unroll
    for (int j = 0; j < 16; j++)
        #pragma unroll
        for (int t = 0; t < 4; t++) acc[j][t] = 0.f;

    #pragma unroll
    for (int kk = 0; kk < 8; ++kk) {
        const int kw = kk * 8 + qq;
        const int r0 = wbase + g;
        uint32_t ah[4], al[4];
        ah[0] = AHw[r0 * 68 + kw];       ah[1] = AHw[(r0 + 8) * 68 + kw];
        ah[2] = AHw[r0 * 68 + kw + 4];   ah[3] = AHw[(r0 + 8) * 68 + kw + 4];
        al[0] = ALw[r0 * 68 + kw];       al[1] = ALw[(r0 + 8) * 68 + kw];
        al[2] = ALw[r0 * 68 + kw + 4];   al[3] = ALw[(r0 + 8) * 68 + kw + 4];
        #pragma unroll
        for (int j = 0; j < 16; ++j) {
            const int n = j * 8 + g;
            uint32_t bh[2] = { BHw[n * 68 + kw], BHw[n * 68 + kw + 4] };
            uint32_t bl[2] = { BLw[n * 68 + kw], BLw[n * 68 + kw + 4] };
            mma_bf16(acc[j], ah, bh);
            mma_bf16(acc[j], ah, bl);
            mma_bf16(acc[j], al, bh);
        }
    }
    __syncthreads();   // all warps done reading B (Wg)

    // ---- issue W[q|k|v] hi/lo -> B (192 rows), overlapped with epilogue ----
    {
        const char* wh = reinterpret_cast<const char*>(g_wqkvh);
        const char* wl = reinterpret_cast<const char*>(g_wqkvl);
        for (int i = tid; i < 3072; i += 256) {
            int row = i >> 4, ch = i & 15;
            uint32_t dof = (uint32_t)(row * 272 + ch * 16);
            cp_async16(sbase + 69632 + dof,  wh + row * 256 + ch * 16);
            cp_async16(sbase + 121856 + dof, wl + row * 256 + ch * 16);
        }
        CP_COMMIT();
    }

    // ---- gate epilogue: xg = x * sigmoid(gate + bg), rewrite A (own rows) ----
    #pragma unroll
    for (int j = 0; j < 16; ++j) {
        const int col = j * 8 + q2;
        #pragma unroll
        for (int hf = 0; hf < 2; ++hf) {
            const int r = wbase + g + hf * 8;
            __nv_bfloat162 hw = *reinterpret_cast<__nv_bfloat162*>(&AH[r * 136 + col]);
            __nv_bfloat162 lw = *reinterpret_cast<__nv_bfloat162*>(&AL[r * 136 + col]);
            float x0 = __bfloat162float(hw.x) + __bfloat162float(lw.x);
            float x1 = __bfloat162float(hw.y) + __bfloat162float(lw.y);
            float c0 = acc[j][hf * 2 + 0], c1 = acc[j][hf * 2 + 1];
            float g0 = 1.f / (1.f + __expf(-(c0 + bgs[col])));
            float g1 = 1.f / (1.f + __expf(-(c1 + bgs[col + 1])));
            uint32_t hiw, low;
            split_pack(x0 * g0, x1 * g1, hiw, low);
            *reinterpret_cast<uint32_t*>(&AH[r * 136 + col]) = hiw;
            *reinterpret_cast<uint32_t*>(&AL[r * 136 + col]) = low;
        }
    }
    CP_WAIT0();
    __syncthreads();

    // ---- phase 2: [q|k|v] = xg @ W (N=192) ----
    float acc2[24][4];
    #pragma unroll
    for (int j = 0; j < 24; j++)
        #pragma unroll
        for (int t = 0; t < 4; t++) acc2[j][t] = 0.f;

    #pragma unroll
    for (int kk = 0; kk < 8; ++kk) {
        const int kw = kk * 8 + qq;
        const int r0 = wbase + g;
        uint32_t ah[4], al[4];
        ah[0] = AHw[r0 * 68 + kw];       ah[1] = AHw[(r0 + 8) * 68 + kw];
        ah[2] = AHw[r0 * 68 + kw + 4];   ah[3] = AHw[(r0 + 8) * 68 + kw + 4];
        al[0] = ALw[r0 * 68 + kw];       al[1] = ALw[(r0 + 8) * 68 + kw];
        al[2] = ALw[r0 * 68 + kw + 4];   al[3] = ALw[(r0 + 8) * 68 + kw + 4];
        #pragma unroll
        for (int j = 0; j < 24; ++j) {
            const int n = j * 8 + g;
            uint32_t bh[2] = { BHw[n * 68 + kw], BHw[n * 68 + kw + 4] };
            uint32_t bl[2] = { BLw[n * 68 + kw], BLw[n * 68 + kw + 4] };
            mma_bf16(acc2[j], ah, bh);
            mma_bf16(acc2[j], ah, bl);
            mma_bf16(acc2[j], al, bh);
        }
    }
    __syncthreads();   // all A reads done before vT overlay writes

    // ---- epilogue: q (scaled) & k -> [B][T][H] bf16 hi/lo; v -> vT smem ----
    uint32_t* gqh = reinterpret_cast<uint32_t*>(g_qhi);
    uint32_t* gql = reinterpret_cast<uint32_t*>(g_qlo);
    uint32_t* gkh = reinterpret_cast<uint32_t*>(g_khi);
    uint32_t* gkl = reinterpret_cast<uint32_t*>(g_klo);
    #pragma unroll
    for (int j = 0; j < 8; ++j) {
        const int h = j * 8 + q2;
        #pragma unroll
        for (int hf = 0; hf < 2; ++hf) {
            const int r = wbase + g + hf * 8;
            uint32_t hiw, low;
            split_pack(acc2[j][hf * 2] * SCALE, acc2[j][hf * 2 + 1] * SCALE, hiw, low);
            size_t widx = (size_t)(tok0 + r) * 32 + (h >> 1);
            gqh[widx] = hiw; gql[widx] = low;
        }
    }
    #pragma unroll
    for (int j = 8; j < 16; ++j) {
        const int h = (j - 8) * 8 + q2;
        #pragma unroll
        for (int hf = 0; hf < 2; ++hf) {
            const int r = wbase + g + hf * 8;
            uint32_t hiw, low;
            split_pack(acc2[j][hf * 2], acc2[j][hf * 2 + 1], hiw, low);
            size_t widx = (size_t)(tok0 + r) * 32 + (h >> 1);
            gkh[widx] = hiw; gkl[widx] = low;
        }
    }
    #pragma unroll
    for (int j = 16; j < 24; ++j) {
        const int h = (j - 16) * 8 + q2;
        const int r = wbase + g;
        vT[h * 132 + r]           = acc2[j][0];
        vT[(h + 1) * 132 + r]     = acc2[j][1];
        vT[h * 132 + r + 8]       = acc2[j][2];
        vT[(h + 1) * 132 + r + 8] = acc2[j][3];
    }
    __syncthreads();

    // ---- v: coalesced bf16 hi/lo stores to [B][H][T] ----
    uint32_t* gvh = reinterpret_cast<uint32_t*>(g_vhi);
    uint32_t* gvl = reinterpret_cast<uint32_t*>(g_vlo);
    for (int i = tid; i < 64 * 64; i += 256) {
        int h = i >> 6, tw = i & 63;
        int t = tw * 2;
        uint32_t hiw, low;
        split_pack(vT[h * 132 + t], vT[h * 132 + t + 1], hiw, low);
        size_t widx = ((size_t)bb * 64 + h) * 256 + ((t0 + t) >> 1);
        gvh[widx] = hiw; gvl[widx] = low;
    }
}

// ---------------------------------------------------------------------------
// Kernel 2: causal flash attention, bf16x3 HMMA, cp.async double-buffered K/V.
// grid (4 q-tiles, 128 batches), 256 threads (8 warps x 16 q-rows).
// smem words: QH 4608 @0, QL 4608 @4608,
//   buf b in {0,1} at 9216 + b*17920: KH 4608, KL 4608, VH 4352, VL 4352.
// total 45056 words = 180224 B.
// ---------------------------------------------------------------------------
#define K2_SMEM 180224

__global__ __launch_bounds__(256, 1)
void head_k2_attn(float* __restrict__ out)
{
    extern __shared__ char smc[];
    const uint32_t sbase = smem_u32(smc);
    uint32_t* S = reinterpret_cast<uint32_t*>(smc);
    uint32_t* QHw = S;
    uint32_t* QLw = S + 4608;

    const int tid   = threadIdx.x;
    const int wid   = tid >> 5;
    const int lane  = tid & 31;
    const int g     = lane >> 2;
    const int qq    = lane & 3;
    const int q2    = qq * 2;
    const int wbase = wid * 16;
    const int qt    = blockIdx.x;
    const int b     = blockIdx.y;
    const int q0    = qt * 128;

    const uint32_t* gqh = reinterpret_cast<const uint32_t*>(g_qhi);
    const uint32_t* gql = reinterpret_cast<const uint32_t*>(g_qlo);
    const uint32_t* gkh = reinterpret_cast<const uint32_t*>(g_khi);
    const uint32_t* gkl = reinterpret_cast<const uint32_t*>(g_klo);
    const uint32_t* gvh = reinterpret_cast<const uint32_t*>(g_vhi);
    const uint32_t* gvl = reinterpret_cast<const uint32_t*>(g_vlo);

    // ---- issue Q (pre-scaled) ----
    {
        size_t qbase = ((size_t)b * 512 + q0) * 32;
        for (int i = tid; i < 1024; i += 256) {
            int row = i >> 3, cw = (i & 7) * 4;
            uint32_t dof = (uint32_t)(row * 36 + cw) * 4;
            cp_async16(sbase + dof,            gqh + qbase + row * 32 + cw);
            cp_async16(sbase + 4608 * 4 + dof, gql + qbase + row * 32 + cw);
        }
    }
    // ---- issue K/V tile 0 into buffer 0, single commit with Q ----
    {
        size_t kbase = (size_t)b * 512 * 32;
        size_t vbase = (size_t)b * 64 * 256;
        const uint32_t bufb = (9216u) * 4;
        for (int i = tid; i < 1024; i += 256) {
            int row = i >> 3, cw = (i & 7) * 4;
            uint32_t dof = bufb + (uint32_t)(row * 36 + cw) * 4;
            cp_async16(sbase + dof,            gkh + kbase + row * 32 + cw);
            cp_async16(sbase + dof + 4608 * 4, gkl + kbase + row * 32 + cw);
        }
        for (int i = tid; i < 1024; i += 256) {
            int h = i >> 4, cw = (i & 15) * 4;
            uint32_t dof = bufb + 9216u * 4 + (uint32_t)(h * 68 + cw) * 4;
            cp_async16(sbase + dof,            gvh + vbase + h * 256 + cw);
            cp_async16(sbase + dof + 4352 * 4, gvl + vbase + h * 256 + cw);
        }
        CP_COMMIT();
    }

    uint32_t qh[4][4], ql[4][4];
    float o[8][4];
    #pragma unroll
    for (int j = 0; j < 8; j++)
        #pragma unroll
        for (int t = 0; t < 4; t++) o[j][t] = 0.f;
    float m0 = -1e30f, m1 = -1e30f, l0 = 0.f, l1 = 0.f;

    for (int jt = 0; jt <= qt; ++jt) {
        CP_WAIT0();
        __syncthreads();

        if (jt == 0) {
            // cache Q fragments once (k=64 -> 4 ksteps)
            #pragma unroll
            for (int kk = 0; kk < 4; ++kk) {
                const int kw = kk * 8 + qq;
                const int r0 = wbase + g;
                qh[kk][0] = QHw[r0 * 36 + kw];     qh[kk][1] = QHw[(r0 + 8) * 36 + kw];
                qh[kk][2] = QHw[r0 * 36 + kw + 4]; qh[kk][3] = QHw[(r0 + 8) * 36 + kw + 4];
                ql[kk][0] = QLw[r0 * 36 + kw];     ql[kk][1] = QLw[(r0 + 8) * 36 + kw];
                ql[kk][2] = QLw[r0 * 36 + kw + 4]; ql[kk][3] = QLw[(r0 + 8) * 36 + kw + 4];
            }
        }

        // ---- prefetch next tile into the other buffer ----
        if (jt < qt) {
            const int nk0 = (jt + 1) * 128;
            size_t kbase = ((size_t)b * 512 + nk0) * 32;
            size_t vbase = (size_t)b * 64 * 256 + (nk0 >> 1);
            const uint32_t bufb = (9216u + ((jt + 1) & 1) * 17920u) * 4;
            for (int i = tid; i < 1024; i += 256) {
                int row = i >> 3, cw = (i & 7) * 4;
                uint32_t dof = bufb + (uint32_t)(row * 36 + cw) * 4;
                cp_async16(sbase + dof,            gkh + kbase + row * 32 + cw);
                cp_async16(sbase + dof + 4608 * 4, gkl + kbase + row * 32 + cw);
            }
            for (int i = tid; i < 1024; i += 256) {
                int h = i >> 4, cw = (i & 15) * 4;
                uint32_t dof = bufb + 9216u * 4 + (uint32_t)(h * 68 + cw) * 4;
                cp_async16(sbase + dof,            gvh + vbase + h * 256 + cw);
                cp_async16(sbase + dof + 4352 * 4, gvl + vbase + h * 256 + cw);
            }
            CP_COMMIT();
        }

        const uint32_t* KHw = S + 9216 + (jt & 1) * 17920;
        const uint32_t* KLw = KHw + 4608;
        const uint32_t* VHw = KHw + 9216;
        const uint32_t* VLw = KHw + 13568;

        // ---- S = Q K^T (16 rows x 128 keys per warp) ----
        float s[16][4];
        #pragma unroll
        for (int j = 0; j < 16; j++)
            #pragma unroll
            for (int t = 0; t < 4; t++) s[j][t] = 0.f;

        #pragma unroll
        for (int kk = 0; kk < 4; ++kk) {
            const int kw = kk * 8 + qq;
            #pragma unroll
            for (int j = 0; j < 16; ++j) {
                const int n = j * 8 + g;
                uint32_t bh[2] = { KHw[n * 36 + kw], KHw[n * 36 + kw + 4] };
                uint32_t bl[2] = { KLw[n * 36 + kw], KLw[n * 36 + kw + 4] };
                mma_bf16(s[j], qh[kk], bh);
                mma_bf16(s[j], qh[kk], bl);
                mma_bf16(s[j], ql[kk], bh);
            }
        }

        // ---- causal mask on diagonal tile ----
        if (jt == qt) {
            const int r0 = q0 + wbase + g;
            const int k0 = jt * 128;
            #pragma unroll
            for (int j = 0; j < 16; ++j) {
                const int c0 = k0 + j * 8 + q2;
                if (c0     > r0)     s[j][0] = -1e30f;
                if (c0 + 1 > r0)     s[j][1] = -1e30f;
                if (c0     > r0 + 8) s[j][2] = -1e30f;
                if (c0 + 1 > r0 + 8) s[j][3] = -1e30f;
            }
        }

        // ---- online softmax (quad shuffles per row) ----
        float mx0 = -1e30f, mx1 = -1e30f;
        #pragma unroll
        for (int j = 0; j < 16; ++j) {
            mx0 = fmaxf(mx0, fmaxf(s[j][0], s[j][1]));
            mx1 = fmaxf(mx1, fmaxf(s[j][2], s[j][3]));
        }
        mx0 = fmaxf(mx0, __shfl_xor_sync(0xffffffffu, mx0, 1));
        mx0 = fmaxf(mx0, __shfl_xor_sync(0xffffffffu, mx0, 2));
        mx1 = fmaxf(mx1, __shfl_xor_sync(0xffffffffu, mx1, 1));
        mx1 = fmaxf(mx1, __shfl_xor_sync(0xffffffffu, mx1, 2));
        const float mn0 = fmaxf(m0, mx0), mn1 = fmaxf(m1, mx1);
        const float a0 = __expf(m0 - mn0), a1 = __expf(m1 - mn1);
        m0 = mn0; m1 = mn1;
        l0 *= a0; l1 *= a1;
        #pragma unroll
        for (int j = 0; j < 8; ++j) {
            o[j][0] *= a0; o[j][1] *= a0; o[j][2] *= a1; o[j][3] *= a1;
        }
        float s0 = 0.f, s1 = 0.f;
        #pragma unroll
        for (int j = 0; j < 16; ++j) {
            s[j][0] = __expf(s[j][0] - mn0); s0 += s[j][0];
            s[j][1] = __expf(s[j][1] - mn0); s0 += s[j][1];
            s[j][2] = __expf(s[j][2] - mn1); s1 += s[j][2];
            s[j][3] = __expf(s[j][3] - mn1); s1 += s[j][3];
        }
        s0 += __shfl_xor_sync(0xffffffffu, s0, 1);
        s0 += __shfl_xor_sync(0xffffffffu, s0, 2);
        s1 += __shfl_xor_sync(0xffffffffu, s1, 1);
        s1 += __shfl_xor_sync(0xffffffffu, s1, 2);
        l0 += s0; l1 += s1;

        // ---- O += P @ V (lane-local P->A-fragment conversion) ----
        #pragma unroll
        for (int kk2 = 0; kk2 < 8; ++kk2) {
            const int j0 = kk2 * 2, j1 = j0 + 1;
            uint32_t ah[4], al[4];
            ah[0] = pack_bf16(s[j0][0], s[j0][1]);
            ah[1] = pack_bf16(s[j0][2], s[j0][3]);
            ah[2] = pack_bf16(s[j1][0], s[j1][1]);
            ah[3] = pack_bf16(s[j1][2], s[j1][3]);
            al[0] = pack_bf16(bf16_residual(s[j0][0]), bf16_residual(s[j0][1]));
            al[1] = pack_bf16(bf16_residual(s[j0][2]), bf16_residual(s[j0][3]));
            al[2] = pack_bf16(bf16_residual(s[j1][0]), bf16_residual(s[j1][1]));
            al[3] = pack_bf16(bf16_residual(s[j1][2]), bf16_residual(s[j1][3]));
            #pragma unroll
            for (int jn = 0; jn < 8; ++jn) {
                const int hN = jn * 8 + g;
                uint32_t vh[2] = { VHw[hN * 68 + kk2 * 8 + qq],
                                   VHw[hN * 68 + kk2 * 8 + qq + 4] };
                uint32_t vl[2] = { VLw[hN * 68 + kk2 * 8 + qq],
                                   VLw[hN * 68 + kk2 * 8 + qq + 4] };
                mma_bf16(o[jn], ah, vh);
                mma_bf16(o[jn], ah, vl);
                mma_bf16(o[jn], al, vh);
            }
        }
    }

    // ---- epilogue: out = O / l, [B][T][H] fp32 ----
    const float i0 = 1.f / l0, i1 = 1.f / l1;
    const int r0 = q0 + wbase + g;
    const size_t ob = (size_t)b * TSEQ * HDIM;
    #pragma unroll
    for (int jn = 0; jn < 8; ++jn) {
        const int h = jn * 8 + q2;
        float2 v0 = make_float2(o[jn][0] * i0, o[jn][1] * i0);
        float2 v1 = make_float2(o[jn][2] * i1, o[jn][3] * i1);
        *reinterpret_cast<float2*>(out + ob + (size_t)r0 * 64 + h)       = v0;
        *reinterpret_cast<float2*>(out + ob + (size_t)(r0 + 8) * 64 + h) = v1;
    }
}

// ---------------------------------------------------------------------------
extern "C" void kernel_launch(void* const* d_in, const int* in_sizes, int n_in,
                              void* d_out, int out_size)
{
    const float* x  = (const float*)d_in[0];
    const float* Wg = (const float*)d_in[1];
    const float* bg = (const float*)d_in[2];
    const float* Wk = (const float*)d_in[3];
    const float* Wq = (const float*)d_in[4];
    const float* Wv = (const float*)d_in[5];
    float* out = (float*)d_out;

    cudaFuncSetAttribute(head_k1_gate_qkv,
                         cudaFuncAttributeMaxDynamicSharedMemorySize, K1_SMEM);
    cudaFuncSetAttribute(head_k2_attn,
                         cudaFuncAttributeMaxDynamicSharedMemorySize, K2_SMEM);

    head_k0_split<<<160, 256>>>(Wg, Wk, Wq, Wv);
    head_k1_gate_qkv<<<BT / 128, 256, K1_SMEM>>>(x, bg);
    head_k2_attn<<<dim3(4, 128), 256, K2_SMEM>>>(out);
}

// round 7
// speedup vs baseline: 3.8599x; 1.1290x over previous
#include <cuda_runtime.h>
#include <cuda_bf16.h>
#include <cstdint>

// Problem constants
#define BT    65536   // B*T
#define CDIM  128
#define HDIM  64
#define TSEQ  512
#define SCALE 0.088388347648318447f   // 1/sqrt(128)

// q/k scratch bf16 hi/lo in [B][T][H]; v scratch bf16 hi/lo in [B][H][T]
__device__ __nv_bfloat16 g_qhi[BT * HDIM];
__device__ __nv_bfloat16 g_qlo[BT * HDIM];
__device__ __nv_bfloat16 g_khi[BT * HDIM];
__device__ __nv_bfloat16 g_klo[BT * HDIM];
__device__ __nv_bfloat16 g_vhi[BT * HDIM];
__device__ __nv_bfloat16 g_vlo[BT * HDIM];

// pre-split weight images (k0 output), row-major [n][k], k stride 128 bf16
__device__ __nv_bfloat16 g_wgh[128 * 128];
__device__ __nv_bfloat16 g_wgl[128 * 128];
__device__ __nv_bfloat16 g_wqkvh[192 * 128];
__device__ __nv_bfloat16 g_wqkvl[192 * 128];

// ---------------------------------------------------------------------------
// helpers
// ---------------------------------------------------------------------------
__device__ __forceinline__ uint32_t smem_u32(const void* p) {
    uint32_t a;
    asm("{ .reg .u64 t; cvta.to.shared.u64 t, %1; cvt.u32.u64 %0, t; }"
        : "=r"(a) : "l"(p));
    return a;
}
__device__ __forceinline__ uint32_t pack_bf16(float lo, float hi) {
    uint32_t r;
    asm("cvt.rn.bf16x2.f32 %0, %1, %2;" : "=r"(r) : "f"(hi), "f"(lo));
    return r;
}
__device__ __forceinline__ float bf16_residual(float v) {
    return v - __bfloat162float(__float2bfloat16(v));
}
__device__ __forceinline__ void split_pack(float v0, float v1,
                                           uint32_t& hi, uint32_t& lo) {
    __nv_bfloat16 h0 = __float2bfloat16(v0);
    __nv_bfloat16 h1 = __float2bfloat16(v1);
    __nv_bfloat162 hh; hh.x = h0; hh.y = h1;
    hi = *reinterpret_cast<uint32_t*>(&hh);
    lo = pack_bf16(v0 - __bfloat162float(h0), v1 - __bfloat162float(h1));
}
__device__ __forceinline__ void mma_bf16(float* d, const uint32_t* a,
                                         const uint32_t* b) {
    asm volatile(
        "mma.sync.aligned.m16n8k16.row.col.f32.bf16.bf16.f32 "
        "{%0,%1,%2,%3}, {%4,%5,%6,%7}, {%8,%9}, {%0,%1,%2,%3};"
        : "+f"(d[0]), "+f"(d[1]), "+f"(d[2]), "+f"(d[3])
        : "r"(a[0]), "r"(a[1]), "r"(a[2]), "r"(a[3]), "r"(b[0]), "r"(b[1]));
}
__device__ __forceinline__ void cp_async16(uint32_t smem_dst, const void* gsrc) {
    asm volatile("cp.async.cg.shared.global [%0], [%1], 16;"
                 :: "r"(smem_dst), "l"(gsrc) : "memory");
}
#define CP_COMMIT() asm volatile("cp.async.commit_group;" ::: "memory")
#define CP_WAIT0()  asm volatile("cp.async.wait_group 0;" ::: "memory")

// ---------------------------------------------------------------------------
// Kernel 0: one-time weight split into bf16 hi/lo global images.
// ---------------------------------------------------------------------------
__global__ __launch_bounds__(256, 4)
void head_k0_split(const float* __restrict__ Wg,
                   const float* __restrict__ Wk,
                   const float* __restrict__ Wq,
                   const float* __restrict__ Wv)
{
    int i = blockIdx.x * 256 + threadIdx.x;
    if (i < 128 * 128) {
        int d = i >> 7, c = i & 127;
        float v = Wg[c * 128 + d];
        __nv_bfloat16 h = __float2bfloat16(v);
        g_wgh[i] = h;
        g_wgl[i] = __float2bfloat16(v - __bfloat162float(h));
    } else if (i < 128 * 128 + 192 * 128) {
        int j = i - 128 * 128;
        int e = j >> 7, c = j & 127;
        float v;
        if (e < 64)       v = Wq[c * 64 + e];
        else if (e < 128) v = Wk[c * 64 + (e - 64)];
        else              v = Wv[c * 64 + (e - 128)];
        __nv_bfloat16 h = __float2bfloat16(v);
        g_wqkvh[j] = h;
        g_wqkvl[j] = __float2bfloat16(v - __bfloat162float(h));
    }
}

// ---------------------------------------------------------------------------
// Kernel 1: gate GEMM + sigmoid-gate + QKV GEMM (bf16x3 HMMA).
// 512 threads = 16 warps = 8 row-groups x 2 N-halves.
// smem: AH @0 (34816), AL @34816, BH @69632 (52224), BL @121856, bg @174080.
// ---------------------------------------------------------------------------
#define K1_SMEM 174592

__global__ __launch_bounds__(512, 1)
void head_k1_gate_qkv(const float* __restrict__ x,
                      const float* __restrict__ bg)
{
    extern __shared__ char smc[];
    const uint32_t sbase = smem_u32(smc);
    __nv_bfloat16* AH = reinterpret_cast<__nv_bfloat16*>(smc);
    __nv_bfloat16* AL = reinterpret_cast<__nv_bfloat16*>(smc + 34816);
    float*         bgs = reinterpret_cast<float*>(smc + 174080);
    float*         vT  = reinterpret_cast<float*>(smc);          // overlay

    uint32_t* AHw = reinterpret_cast<uint32_t*>(AH);
    uint32_t* ALw = reinterpret_cast<uint32_t*>(AL);
    const uint32_t* BHw = reinterpret_cast<const uint32_t*>(smc + 69632);
    const uint32_t* BLw = reinterpret_cast<const uint32_t*>(smc + 121856);

    const int tid   = threadIdx.x;
    const int wid   = tid >> 5;
    const int lane  = tid & 31;
    const int g     = lane >> 2;
    const int qq    = lane & 3;
    const int q2    = qq * 2;
    const int rg    = wid >> 1;         // row group 0..7
    const int nh    = wid & 1;          // N half
    const int wbase = rg * 16;
    const int tok0  = blockIdx.x * 128;
    const int bb    = tok0 >> 9;
    const int t0    = tok0 & 511;

    // ---- issue Wg hi/lo -> B via cp.async ----
    {
        const char* wh = reinterpret_cast<const char*>(g_wgh);
        const char* wl = reinterpret_cast<const char*>(g_wgl);
        for (int i = tid; i < 2048; i += 512) {
            int row = i >> 4, ch = i & 15;
            uint32_t dof = (uint32_t)(row * 272 + ch * 16);
            cp_async16(sbase + 69632 + dof,  wh + row * 256 + ch * 16);
            cp_async16(sbase + 121856 + dof, wl + row * 256 + ch * 16);
        }
        CP_COMMIT();
    }

    // ---- load + split x -> A hi/lo (float4 vectorized) ----
    for (int i = tid; i < 4096; i += 512) {
        int t = i >> 5, c4 = (i & 31) * 4;
        float4 xv = *reinterpret_cast<const float4*>(
                        x + (size_t)(tok0 + t) * CDIM + c4);
        uint32_t h0, l0w, h1, l1w;
        split_pack(xv.x, xv.y, h0, l0w);
        split_pack(xv.z, xv.w, h1, l1w);
        int widx = t * 68 + (c4 >> 1);
        AHw[widx] = h0; AHw[widx + 1] = h1;
        ALw[widx] = l0w; ALw[widx + 1] = l1w;
    }
    if (tid < 128) bgs[tid] = bg[tid];
    CP_WAIT0();
    __syncthreads();

    // ---- phase 1: gate = x @ Wg (16 rows x 64 cols per warp) ----
    float acc[8][4];
    #pragma unroll
    for (int j = 0; j < 8; j++)
        #pragma unroll
        for (int t = 0; t < 4; t++) acc[j][t] = 0.f;

    #pragma unroll
    for (int kk = 0; kk < 8; ++kk) {
        const int kw = kk * 8 + qq;
        const int r0 = wbase + g;
        uint32_t ah[4], al[4];
        ah[0] = AHw[r0 * 68 + kw];       ah[1] = AHw[(r0 + 8) * 68 + kw];
        ah[2] = AHw[r0 * 68 + kw + 4];   ah[3] = AHw[(r0 + 8) * 68 + kw + 4];
        al[0] = ALw[r0 * 68 + kw];       al[1] = ALw[(r0 + 8) * 68 + kw];
        al[2] = ALw[r0 * 68 + kw + 4];   al[3] = ALw[(r0 + 8) * 68 + kw + 4];
        #pragma unroll
        for (int j = 0; j < 8; ++j) {
            const int n = nh * 64 + j * 8 + g;
            uint32_t bh[2] = { BHw[n * 68 + kw], BHw[n * 68 + kw + 4] };
            uint32_t bl[2] = { BLw[n * 68 + kw], BLw[n * 68 + kw + 4] };
            mma_bf16(acc[j], ah, bh);
            mma_bf16(acc[j], ah, bl);
            mma_bf16(acc[j], al, bh);
        }
    }
    __syncthreads();   // all warps done reading B (Wg)

    // ---- issue W[q|k|v] hi/lo -> B, overlapped with gate epilogue ----
    {
        const char* wh = reinterpret_cast<const char*>(g_wqkvh);
        const char* wl = reinterpret_cast<const char*>(g_wqkvl);
        for (int i = tid; i < 3072; i += 512) {
            int row = i >> 4, ch = i & 15;
            uint32_t dof = (uint32_t)(row * 272 + ch * 16);
            cp_async16(sbase + 69632 + dof,  wh + row * 256 + ch * 16);
            cp_async16(sbase + 121856 + dof, wl + row * 256 + ch * 16);
        }
        CP_COMMIT();
    }

    // ---- gate epilogue: xg = x * sigmoid(gate + bg), rewrite A (own cells) ----
    #pragma unroll
    for (int j = 0; j < 8; ++j) {
        const int col = nh * 64 + j * 8 + q2;
        #pragma unroll
        for (int hf = 0; hf < 2; ++hf) {
            const int r = wbase + g + hf * 8;
            __nv_bfloat162 hw = *reinterpret_cast<__nv_bfloat162*>(&AH[r * 136 + col]);
            __nv_bfloat162 lw = *reinterpret_cast<__nv_bfloat162*>(&AL[r * 136 + col]);
            float x0 = __bfloat162float(hw.x) + __bfloat162float(lw.x);
            float x1 = __bfloat162float(hw.y) + __bfloat162float(lw.y);
            float c0 = acc[j][hf * 2 + 0], c1 = acc[j][hf * 2 + 1];
            float g0 = 1.f / (1.f + __expf(-(c0 + bgs[col])));
            float g1 = 1.f / (1.f + __expf(-(c1 + bgs[col + 1])));
            uint32_t hiw, low;
            split_pack(x0 * g0, x1 * g1, hiw, low);
            *reinterpret_cast<uint32_t*>(&AH[r * 136 + col]) = hiw;
            *reinterpret_cast<uint32_t*>(&AL[r * 136 + col]) = low;
        }
    }
    CP_WAIT0();
    __syncthreads();

    // ---- phase 2: [q|k|v] = xg @ W (16 rows x 96 cols per warp) ----
    float acc2[12][4];
    #pragma unroll
    for (int j = 0; j < 12; j++)
        #pragma unroll
        for (int t = 0; t < 4; t++) acc2[j][t] = 0.f;

    #pragma unroll
    for (int kk = 0; kk < 8; ++kk) {
        const int kw = kk * 8 + qq;
        const int r0 = wbase + g;
        uint32_t ah[4], al[4];
        ah[0] = AHw[r0 * 68 + kw];       ah[1] = AHw[(r0 + 8) * 68 + kw];
        ah[2] = AHw[r0 * 68 + kw + 4];   ah[3] = AHw[(r0 + 8) * 68 + kw + 4];
        al[0] = ALw[r0 * 68 + kw];       al[1] = ALw[(r0 + 8) * 68 + kw];
        al[2] = ALw[r0 * 68 + kw + 4];   al[3] = ALw[(r0 + 8) * 68 + kw + 4];
        #pragma unroll
        for (int j = 0; j < 12; ++j) {
            const int n = nh * 96 + j * 8 + g;
            uint32_t bh[2] = { BHw[n * 68 + kw], BHw[n * 68 + kw + 4] };
            uint32_t bl[2] = { BLw[n * 68 + kw], BLw[n * 68 + kw + 4] };
            mma_bf16(acc2[j], ah, bh);
            mma_bf16(acc2[j], ah, bl);
            mma_bf16(acc2[j], al, bh);
        }
    }
    __syncthreads();   // all A reads done before vT overlay writes

    // ---- epilogue: route by e = nh*96 + j*8 + q2 ----
    uint32_t* gqh = reinterpret_cast<uint32_t*>(g_qhi);
    uint32_t* gql = reinterpret_cast<uint32_t*>(g_qlo);
    uint32_t* gkh = reinterpret_cast<uint32_t*>(g_khi);
    uint32_t* gkl = reinterpret_cast<uint32_t*>(g_klo);
    #pragma unroll
    for (int j = 0; j < 12; ++j) {
        const int e = nh * 96 + j * 8 + q2;
        if (e < 64) {            // q (pre-scaled)
            #pragma unroll
            for (int hf = 0; hf < 2; ++hf) {
                const int r = wbase + g + hf * 8;
                uint32_t hiw, low;
                split_pack(acc2[j][hf * 2] * SCALE, acc2[j][hf * 2 + 1] * SCALE,
                           hiw, low);
                size_t widx = (size_t)(tok0 + r) * 32 + (e >> 1);
                gqh[widx] = hiw; gql[widx] = low;
            }
        } else if (e < 128) {    // k
            const int h = e - 64;
            #pragma unroll
            for (int hf = 0; hf < 2; ++hf) {
                const int r = wbase + g + hf * 8;
                uint32_t hiw, low;
                split_pack(acc2[j][hf * 2], acc2[j][hf * 2 + 1], hiw, low);
                size_t widx = (size_t)(tok0 + r) * 32 + (h >> 1);
                gkh[widx] = hiw; gkl[widx] = low;
            }
        } else {                 // v -> vT smem (transpose)
            const int h = e - 128;
            const int r = wbase + g;
            vT[h * 132 + r]           = acc2[j][0];
            vT[(h + 1) * 132 + r]     = acc2[j][1];
            vT[h * 132 + r + 8]       = acc2[j][2];
            vT[(h + 1) * 132 + r + 8] = acc2[j][3];
        }
    }
    __syncthreads();

    // ---- v: coalesced bf16 hi/lo stores to [B][H][T] ----
    uint32_t* gvh = reinterpret_cast<uint32_t*>(g_vhi);
    uint32_t* gvl = reinterpret_cast<uint32_t*>(g_vlo);
    for (int i = tid; i < 64 * 64; i += 512) {
        int h = i >> 6, tw = i & 63;
        int t = tw * 2;
        uint32_t hiw, low;
        split_pack(vT[h * 132 + t], vT[h * 132 + t + 1], hiw, low);
        size_t widx = ((size_t)bb * 64 + h) * 256 + ((t0 + t) >> 1);
        gvh[widx] = hiw; gvl[widx] = low;
    }
}

// ---------------------------------------------------------------------------
// Kernel 2: causal flash attention, bf16x3 HMMA, split-K warps + cp.async.
// 512 threads = 16 warps = 8 q-groups (16 rows) x 2 key-halves (64 keys).
// smem words: QH 4608 @0, QL @4608; buf b at 9216 + b*17920:
//   KH 4608, KL 4608, VH 4352, VL 4352. total 45056 words = 180224 B.
// ---------------------------------------------------------------------------
#define K2_SMEM 180224

__global__ __launch_bounds__(512, 1)
void head_k2_attn(float* __restrict__ out)
{
    extern __shared__ char smc[];
    const uint32_t sbase = smem_u32(smc);
    uint32_t* S = reinterpret_cast<uint32_t*>(smc);
    const uint32_t* QHw = S;
    const uint32_t* QLw = S + 4608;

    const int tid   = threadIdx.x;
    const int wid   = tid >> 5;
    const int lane  = tid & 31;
    const int g     = lane >> 2;
    const int qq    = lane & 3;
    const int q2    = qq * 2;
    const int qg    = wid >> 1;        // q group 0..7
    const int kh    = wid & 1;         // key half
    const int wbase = qg * 16;
    const int qt    = blockIdx.x;
    const int b     = blockIdx.y;
    const int q0    = qt * 128;

    const uint32_t* gqh = reinterpret_cast<const uint32_t*>(g_qhi);
    const uint32_t* gql = reinterpret_cast<const uint32_t*>(g_qlo);
    const uint32_t* gkh = reinterpret_cast<const uint32_t*>(g_khi);
    const uint32_t* gkl = reinterpret_cast<const uint32_t*>(g_klo);
    const uint32_t* gvh = reinterpret_cast<const uint32_t*>(g_vhi);
    const uint32_t* gvl = reinterpret_cast<const uint32_t*>(g_vlo);

    // ---- issue Q + K/V tile 0, single commit ----
    {
        size_t qbase = ((size_t)b * 512 + q0) * 32;
        for (int i = tid; i < 1024; i += 512) {
            int row = i >> 3, cw = (i & 7) * 4;
            uint32_t dof = (uint32_t)(row * 36 + cw) * 4;
            cp_async16(sbase + dof,            gqh + qbase + row * 32 + cw);
            cp_async16(sbase + 4608 * 4 + dof, gql + qbase + row * 32 + cw);
        }
        size_t kbase = (size_t)b * 512 * 32;
        size_t vbase = (size_t)b * 64 * 256;
        const uint32_t bufb = 9216u * 4;
        for (int i = tid; i < 1024; i += 512) {
            int row = i >> 3, cw = (i & 7) * 4;
            uint32_t dof = bufb + (uint32_t)(row * 36 + cw) * 4;
            cp_async16(sbase + dof,            gkh + kbase + row * 32 + cw);
            cp_async16(sbase + dof + 4608 * 4, gkl + kbase + row * 32 + cw);
        }
        for (int i = tid; i < 1024; i += 512) {
            int h = i >> 4, cw = (i & 15) * 4;
            uint32_t dof = bufb + 9216u * 4 + (uint32_t)(h * 68 + cw) * 4;
            cp_async16(sbase + dof,            gvh + vbase + h * 256 + cw);
            cp_async16(sbase + dof + 4352 * 4, gvl + vbase + h * 256 + cw);
        }
        CP_COMMIT();
    }

    float o[8][4];
    #pragma unroll
    for (int j = 0; j < 8; j++)
        #pragma unroll
        for (int t = 0; t < 4; t++) o[j][t] = 0.f;
    float m0 = -1e30f, m1 = -1e30f, l0 = 0.f, l1 = 0.f;

    for (int jt = 0; jt <= qt; ++jt) {
        CP_WAIT0();
        __syncthreads();

        // prefetch next tile into the other buffer (all warps)
        if (jt < qt) {
            const int nk0 = (jt + 1) * 128;
            size_t kbase = ((size_t)b * 512 + nk0) * 32;
            size_t vbase = (size_t)b * 64 * 256 + (nk0 >> 1);
            const uint32_t bufb = (9216u + ((jt + 1) & 1) * 17920u) * 4;
            for (int i = tid; i < 1024; i += 512) {
                int row = i >> 3, cw = (i & 7) * 4;
                uint32_t dof = bufb + (uint32_t)(row * 36 + cw) * 4;
                cp_async16(sbase + dof,            gkh + kbase + row * 32 + cw);
                cp_async16(sbase + dof + 4608 * 4, gkl + kbase + row * 32 + cw);
            }
            for (int i = tid; i < 1024; i += 512) {
                int h = i >> 4, cw = (i & 15) * 4;
                uint32_t dof = bufb + 9216u * 4 + (uint32_t)(h * 68 + cw) * 4;
                cp_async16(sbase + dof,            gvh + vbase + h * 256 + cw);
                cp_async16(sbase + dof + 4352 * 4, gvl + vbase + h * 256 + cw);
            }
            CP_COMMIT();
        }

        // kh=1 warps whose key range sits entirely above their rows on the
        // diagonal tile: skip (prevents all-masked softmax poisoning)
        if (kh == 1 && jt == qt && qg < 4) continue;

        const uint32_t* KHw = S + 9216 + (jt & 1) * 17920;
        const uint32_t* KLw = KHw + 4608;
        const uint32_t* VHw = KHw + 9216;
        const uint32_t* VLw = KHw + 13568;

        // ---- S = Q K^T (16 rows x 64 keys per warp) ----
        float s[8][4];
        #pragma unroll
        for (int j = 0; j < 8; j++)
            #pragma unroll
            for (int t = 0; t < 4; t++) s[j][t] = 0.f;

        #pragma unroll
        for (int kk = 0; kk < 4; ++kk) {
            const int kw = kk * 8 + qq;
            const int r0w = wbase + g;
            uint32_t qh[4], ql[4];
            qh[0] = QHw[r0w * 36 + kw];     qh[1] = QHw[(r0w + 8) * 36 + kw];
            qh[2] = QHw[r0w * 36 + kw + 4]; qh[3] = QHw[(r0w + 8) * 36 + kw + 4];
            ql[0] = QLw[r0w * 36 + kw];     ql[1] = QLw[(r0w + 8) * 36 + kw];
            ql[2] = QLw[r0w * 36 + kw + 4]; ql[3] = QLw[(r0w + 8) * 36 + kw + 4];
            #pragma unroll
            for (int j = 0; j < 8; ++j) {
                const int n = kh * 64 + j * 8 + g;
                uint32_t bh[2] = { KHw[n * 36 + kw], KHw[n * 36 + kw + 4] };
                uint32_t bl[2] = { KLw[n * 36 + kw], KLw[n * 36 + kw + 4] };
                mma_bf16(s[j], qh, bh);
                mma_bf16(s[j], qh, bl);
                mma_bf16(s[j], ql, bh);
            }
        }

        // ---- causal mask on diagonal tile ----
        if (jt == qt) {
            const int r0 = q0 + wbase + g;
            const int cb = jt * 128 + kh * 64;
            #pragma unroll
            for (int j = 0; j < 8; ++j) {
                const int c0 = cb + j * 8 + q2;
                if (c0     > r0)     s[j][0] = -1e30f;
                if (c0 + 1 > r0)     s[j][1] = -1e30f;
                if (c0     > r0 + 8) s[j][2] = -1e30f;
                if (c0 + 1 > r0 + 8) s[j][3] = -1e30f;
            }
        }

        // ---- online softmax (quad shuffles per row) ----
        float mx0 = -1e30f, mx1 = -1e30f;
        #pragma unroll
        for (int j = 0; j < 8; ++j) {
            mx0 = fmaxf(mx0, fmaxf(s[j][0], s[j][1]));
            mx1 = fmaxf(mx1, fmaxf(s[j][2], s[j][3]));
        }
        mx0 = fmaxf(mx0, __shfl_xor_sync(0xffffffffu, mx0, 1));
        mx0 = fmaxf(mx0, __shfl_xor_sync(0xffffffffu, mx0, 2));
        mx1 = fmaxf(mx1, __shfl_xor_sync(0xffffffffu, mx1, 1));
        mx1 = fmaxf(mx1, __shfl_xor_sync(0xffffffffu, mx1, 2));
        const float mn0 = fmaxf(m0, mx0), mn1 = fmaxf(m1, mx1);
        const float a0 = __expf(m0 - mn0), a1 = __expf(m1 - mn1);
        m0 = mn0; m1 = mn1;
        l0 *= a0; l1 *= a1;
        #pragma unroll
        for (int j = 0; j < 8; ++j) {
            o[j][0] *= a0; o[j][1] *= a0; o[j][2] *= a1; o[j][3] *= a1;
        }
        float s0 = 0.f, s1 = 0.f;
        #pragma unroll
        for (int j = 0; j < 8; ++j) {
            s[j][0] = __expf(s[j][0] - mn0); s0 += s[j][0];
            s[j][1] = __expf(s[j][1] - mn0); s0 += s[j][1];
            s[j][2] = __expf(s[j][2] - mn1); s1 += s[j][2];
            s[j][3] = __expf(s[j][3] - mn1); s1 += s[j][3];
        }
        s0 += __shfl_xor_sync(0xffffffffu, s0, 1);
        s0 += __shfl_xor_sync(0xffffffffu, s0, 2);
        s1 += __shfl_xor_sync(0xffffffffu, s1, 1);
        s1 += __shfl_xor_sync(0xffffffffu, s1, 2);
        l0 += s0; l1 += s1;

        // ---- O += P @ V over this warp's 64 keys ----
        #pragma unroll
        for (int kk2 = 0; kk2 < 4; ++kk2) {
            const int j0 = kk2 * 2, j1 = j0 + 1;
            uint32_t ah[4], al[4];
            ah[0] = pack_bf16(s[j0][0], s[j0][1]);
            ah[1] = pack_bf16(s[j0][2], s[j0][3]);
            ah[2] = pack_bf16(s[j1][0], s[j1][1]);
            ah[3] = pack_bf16(s[j1][2], s[j1][3]);
            al[0] = pack_bf16(bf16_residual(s[j0][0]), bf16_residual(s[j0][1]));
            al[1] = pack_bf16(bf16_residual(s[j0][2]), bf16_residual(s[j0][3]));
            al[2] = pack_bf16(bf16_residual(s[j1][0]), bf16_residual(s[j1][1]));
            al[3] = pack_bf16(bf16_residual(s[j1][2]), bf16_residual(s[j1][3]));
            const int kwv = kh * 32 + kk2 * 8 + qq;
            #pragma unroll
            for (int jn = 0; jn < 8; ++jn) {
                const int hN = jn * 8 + g;
                uint32_t vh[2] = { VHw[hN * 68 + kwv], VHw[hN * 68 + kwv + 4] };
                uint32_t vl[2] = { VLw[hN * 68 + kwv], VLw[hN * 68 + kwv + 4] };
                mma_bf16(o[jn], ah, vh);
                mma_bf16(o[jn], ah, vl);
                mma_bf16(o[jn], al, vh);
            }
        }
    }

    // ---- merge key-halves through smem, then write out ----
    __syncthreads();                          // everyone done with K/V buffers
    float* oB = reinterpret_cast<float*>(smc);          // 128 x 68 (Q region)
    float* mB = reinterpret_cast<float*>(S + 9216);     // 128
    float* lB = mB + 128;

    if (kh == 1) {
        #pragma unroll
        for (int j = 0; j < 8; ++j) {
            const int h = j * 8 + q2;
            oB[(wbase + g) * 68 + h]         = o[j][0];
            oB[(wbase + g) * 68 + h + 1]     = o[j][1];
            oB[(wbase + 8 + g) * 68 + h]     = o[j][2];
            oB[(wbase + 8 + g) * 68 + h + 1] = o[j][3];
        }
        if (qq == 0) {
            mB[wbase + g] = m0;     lB[wbase + g] = l0;
            mB[wbase + 8 + g] = m1; lB[wbase + 8 + g] = l1;
        }
    }
    __syncthreads();

    if (kh == 0) {
        const int r0 = wbase + g, r1 = r0 + 8;
        const float mb0 = mB[r0], mb1 = mB[r1];
        const float mF0 = fmaxf(m0, mb0), mF1 = fmaxf(m1, mb1);
        const float aA0 = __expf(m0 - mF0), aB0 = __expf(mb0 - mF0);
        const float aA1 = __expf(m1 - mF1), aB1 = __expf(mb1 - mF1);
        const float i0 = 1.f / (l0 * aA0 + lB[r0] * aB0);
        const float i1 = 1.f / (l1 * aA1 + lB[r1] * aB1);
        const int gr0 = q0 + r0;
        const size_t ob = (size_t)b * TSEQ * HDIM;
        #pragma unroll
        for (int jn = 0; jn < 8; ++jn) {
            const int h = jn * 8 + q2;
            float2 v0, v1;
            v0.x = (o[jn][0] * aA0 + oB[r0 * 68 + h]     * aB0) * i0;
            v0.y = (o[jn][1] * aA0 + oB[r0 * 68 + h + 1] * aB0) * i0;
            v1.x = (o[jn][2] * aA1 + oB[r1 * 68 + h]     * aB1) * i1;
            v1.y = (o[jn][3] * aA1 + oB[r1 * 68 + h + 1] * aB1) * i1;
            *reinterpret_cast<float2*>(out + ob + (size_t)gr0 * 64 + h)       = v0;
            *reinterpret_cast<float2*>(out + ob + (size_t)(gr0 + 8) * 64 + h) = v1;
        }
    }
}

// ---------------------------------------------------------------------------
extern "C" void kernel_launch(void* const* d_in, const int* in_sizes, int n_in,
                              void* d_out, int out_size)
{
    const float* x  = (const float*)d_in[0];
    const float* Wg = (const float*)d_in[1];
    const float* bg = (const float*)d_in[2];
    const float* Wk = (const float*)d_in[3];
    const float* Wq = (const float*)d_in[4];
    const float* Wv = (const float*)d_in[5];
    float* out = (float*)d_out;

    cudaFuncSetAttribute(head_k1_gate_qkv,
                         cudaFuncAttributeMaxDynamicSharedMemorySize, K1_SMEM);
    cudaFuncSetAttribute(head_k2_attn,
                         cudaFuncAttributeMaxDynamicSharedMemorySize, K2_SMEM);

    head_k0_split<<<160, 256>>>(Wg, Wk, Wq, Wv);
    head_k1_gate_qkv<<<BT / 128, 512, K1_SMEM>>>(x, bg);
    head_k2_attn<<<dim3(4, 128), 512, K2_SMEM>>>(out);
}